// round 1
// baseline (speedup 1.0000x reference)
#include <cuda_runtime.h>
#include <math.h>

#define NN 100000
#define NE 1200000
#define D  64
#define NG 512

// -------- scratch (device globals; no allocation) --------
static __device__ float g_xs [NN * D];   // scaled features (x * ns)
static __device__ float g_agg[NN * D];   // scatter-add accumulator
static __device__ float g_h1 [NN * D];   // layer output
static __device__ float g_ns [NN];
static __device__ float g_nd [NN];
static __device__ int   g_dego[NN];
static __device__ int   g_degi[NN];
static __device__ float g_psum[NG * D];
static __device__ float g_pmax[NG * D];
static __device__ int   g_pcnt[NG];

// -------- init / degrees --------
__global__ void k_zero() {
    int i = blockIdx.x * blockDim.x + threadIdx.x;
    if (i < NN) { g_dego[i] = 0; g_degi[i] = 0; }
    if (i < NG * D) { g_psum[i] = 0.f; g_pmax[i] = 0.f; }
    if (i < NG) g_pcnt[i] = 0;
}

__global__ void k_deg(const int* __restrict__ src, const int* __restrict__ dst) {
    int e = blockIdx.x * blockDim.x + threadIdx.x;
    if (e < NE) {
        atomicAdd(&g_dego[src[e]], 1);
        atomicAdd(&g_degi[dst[e]], 1);
    }
}

__global__ void k_norm() {
    int i = blockIdx.x * blockDim.x + threadIdx.x;
    if (i < NN) {
        g_ns[i] = rsqrtf((float)max(g_dego[i], 1));
        g_nd[i] = rsqrtf((float)max(g_degi[i], 1));
    }
}

// -------- scale features by ns, zero agg (fused) --------
__global__ void k_scale(const float* __restrict__ x, int use_h1) {
    int i = blockIdx.x * blockDim.x + threadIdx.x;   // over NN*16 float4s
    if (i < NN * 16) {
        float4 v = use_h1 ? ((const float4*)g_h1)[i] : ((const float4*)x)[i];
        float s = g_ns[i >> 4];
        v.x *= s; v.y *= s; v.z *= s; v.w *= s;
        ((float4*)g_xs)[i] = v;
        ((float4*)g_agg)[i] = make_float4(0.f, 0.f, 0.f, 0.f);
    }
}

// -------- edge scatter: agg[dst] += xs[src], vectorized red.v4 --------
__global__ void k_scatter(const int* __restrict__ src, const int* __restrict__ dst) {
    int i = blockIdx.x * blockDim.x + threadIdx.x;   // over NE*16 (16 float4 per edge)
    if (i < NE * 16) {
        int e = i >> 4;
        int c = i & 15;
        int s = __ldg(&src[e]);
        int d = __ldg(&dst[e]);
        float4 v = ((const float4*)g_xs)[s * 16 + c];
        float* p = &g_agg[d * 64 + c * 4];
        asm volatile("red.global.add.v4.f32 [%0], {%1,%2,%3,%4};"
                     :: "l"(p), "f"(v.x), "f"(v.y), "f"(v.z), "f"(v.w)
                     : "memory");
    }
}

// -------- node update: h1 = relu(LN((agg*nd) @ W + b)) --------
__global__ void k_node(const float* __restrict__ W, const float* __restrict__ b,
                       const float* __restrict__ gm, const float* __restrict__ bt) {
    __shared__ float Ws[64 * 64];
    int tid = threadIdx.x;
    for (int i = tid; i < 64 * 64; i += blockDim.x) Ws[i] = W[i];
    __syncthreads();

    int lane  = tid & 31;
    int wid   = tid >> 5;
    int nwarp = blockDim.x >> 5;

    for (int n = blockIdx.x * nwarp + wid; n < NN; n += gridDim.x * nwarp) {
        float ndv = g_nd[n];
        float a0 = g_agg[n * 64 + lane]      * ndv;
        float a1 = g_agg[n * 64 + 32 + lane] * ndv;
        float acc0 = b[lane];
        float acc1 = b[lane + 32];
        #pragma unroll
        for (int k = 0; k < 32; k++) {
            float xk = __shfl_sync(0xffffffffu, a0, k);
            acc0 += xk * Ws[k * 64 + lane];
            acc1 += xk * Ws[k * 64 + 32 + lane];
        }
        #pragma unroll
        for (int k = 0; k < 32; k++) {
            float xk = __shfl_sync(0xffffffffu, a1, k);
            acc0 += xk * Ws[(k + 32) * 64 + lane];
            acc1 += xk * Ws[(k + 32) * 64 + 32 + lane];
        }
        // LayerNorm over 64 (2 values/lane) + ReLU
        float s = acc0 + acc1;
        #pragma unroll
        for (int o = 16; o; o >>= 1) s += __shfl_xor_sync(0xffffffffu, s, o);
        float mean = s * (1.f / 64.f);
        float d0 = acc0 - mean, d1 = acc1 - mean;
        float vv = d0 * d0 + d1 * d1;
        #pragma unroll
        for (int o = 16; o; o >>= 1) vv += __shfl_xor_sync(0xffffffffu, vv, o);
        float inv = rsqrtf(vv * (1.f / 64.f) + 1e-5f);
        float y0 = d0 * inv * gm[lane]      + bt[lane];
        float y1 = d1 * inv * gm[lane + 32] + bt[lane + 32];
        g_h1[n * 64 + lane]      = fmaxf(y0, 0.f);
        g_h1[n * 64 + 32 + lane] = fmaxf(y1, 0.f);
    }
}

// -------- per-graph mean/max pooling --------
__global__ void k_pool(const int* __restrict__ gid) {
    int i = blockIdx.x * blockDim.x + threadIdx.x;   // over NN*64
    if (i < NN * 64) {
        int n = i >> 6, k = i & 63;
        int g = __ldg(&gid[n]);
        float v = g_h1[i];
        atomicAdd(&g_psum[g * 64 + k], v);
        // v >= 0 (post-ReLU) and buffer init 0 -> int-compare atomicMax is valid
        atomicMax((int*)&g_pmax[g * 64 + k], __float_as_int(v));
        if (k == 0) atomicAdd(&g_pcnt[g], 1);
    }
}

// -------- classifier head: one block (64 threads) per graph --------
__global__ void k_cls(const float* __restrict__ Wc1, const float* __restrict__ bc1,
                      const float* __restrict__ g3,  const float* __restrict__ be3,
                      const float* __restrict__ Wc2, const float* __restrict__ bc2,
                      const float* __restrict__ g4,  const float* __restrict__ be4,
                      const float* __restrict__ Wc3, const float* __restrict__ bc3,
                      float* __restrict__ out) {
    __shared__ float hA[64], hB[64], o1[64], red[64];
    int g = blockIdx.x, t = threadIdx.x;

    float cnt = fmaxf((float)g_pcnt[g], 1.f);
    float mv = g_psum[g * 64 + t] / cnt;
    float xv = g_pmax[g * 64 + t];

    // l2 norm of mean vec
    red[t] = mv * mv; __syncthreads();
    for (int o = 32; o; o >>= 1) { if (t < o) red[t] += red[t + o]; __syncthreads(); }
    float nA = fmaxf(sqrtf(red[0]), 1e-12f); __syncthreads();
    // l2 norm of max vec
    red[t] = xv * xv; __syncthreads();
    for (int o = 32; o; o >>= 1) { if (t < o) red[t] += red[t + o]; __syncthreads(); }
    float nB = fmaxf(sqrtf(red[0]), 1e-12f); __syncthreads();

    hA[t] = mv / nA;
    hB[t] = xv / nB;
    __syncthreads();

    // layer 1: [128] @ Wc1[128,64]
    float acc = bc1[t];
    #pragma unroll 4
    for (int k = 0; k < 64; k++) acc += hA[k] * Wc1[k * 64 + t];
    #pragma unroll 4
    for (int k = 0; k < 64; k++) acc += hB[k] * Wc1[(64 + k) * 64 + t];
    // LN + relu
    red[t] = acc; __syncthreads();
    for (int o = 32; o; o >>= 1) { if (t < o) red[t] += red[t + o]; __syncthreads(); }
    float mean = red[0] * (1.f / 64.f); __syncthreads();
    float dv = acc - mean;
    red[t] = dv * dv; __syncthreads();
    for (int o = 32; o; o >>= 1) { if (t < o) red[t] += red[t + o]; __syncthreads(); }
    float inv = rsqrtf(red[0] * (1.f / 64.f) + 1e-5f); __syncthreads();
    o1[t] = fmaxf(dv * inv * g3[t] + be3[t], 0.f);
    __syncthreads();

    // layer 2: [64] @ Wc2[64,64]
    acc = bc2[t];
    #pragma unroll 4
    for (int k = 0; k < 64; k++) acc += o1[k] * Wc2[k * 64 + t];
    red[t] = acc; __syncthreads();
    for (int o = 32; o; o >>= 1) { if (t < o) red[t] += red[t + o]; __syncthreads(); }
    mean = red[0] * (1.f / 64.f); __syncthreads();
    dv = acc - mean;
    red[t] = dv * dv; __syncthreads();
    for (int o = 32; o; o >>= 1) { if (t < o) red[t] += red[t + o]; __syncthreads(); }
    inv = rsqrtf(red[0] * (1.f / 64.f) + 1e-5f); __syncthreads();
    float o2 = fmaxf(dv * inv * g4[t] + be4[t], 0.f);

    // layer 3: [64] @ Wc3[64,1]
    red[t] = o2 * Wc3[t]; __syncthreads();
    for (int o = 32; o; o >>= 1) { if (t < o) red[t] += red[t + o]; __syncthreads(); }
    if (t == 0) out[g] = red[0] + bc3[0];
}

extern "C" void kernel_launch(void* const* d_in, const int* in_sizes, int n_in,
                              void* d_out, int out_size) {
    const float* h   = (const float*)d_in[0];
    const int*   src = (const int*)  d_in[1];
    const int*   dst = (const int*)  d_in[2];
    const int*   gid = (const int*)  d_in[3];
    const float* W1  = (const float*)d_in[4];
    const float* b1  = (const float*)d_in[5];
    const float* W2  = (const float*)d_in[6];
    const float* b2  = (const float*)d_in[7];
    const float* g1  = (const float*)d_in[8];
    const float* be1 = (const float*)d_in[9];
    const float* g2  = (const float*)d_in[10];
    const float* be2 = (const float*)d_in[11];
    const float* g3  = (const float*)d_in[12];
    const float* be3 = (const float*)d_in[13];
    const float* g4  = (const float*)d_in[14];
    const float* be4 = (const float*)d_in[15];
    const float* Wc1 = (const float*)d_in[16];
    const float* bc1 = (const float*)d_in[17];
    const float* Wc2 = (const float*)d_in[18];
    const float* bc2 = (const float*)d_in[19];
    const float* Wc3 = (const float*)d_in[20];
    const float* bc3 = (const float*)d_in[21];
    float* out = (float*)d_out;

    k_zero<<<(NN + 255) / 256, 256>>>();
    k_deg <<<(NE + 255) / 256, 256>>>(src, dst);
    k_norm<<<(NN + 255) / 256, 256>>>();

    // conv 1
    k_scale  <<<(NN * 16 + 255) / 256, 256>>>(h, 0);
    k_scatter<<<(NE * 16 + 255) / 256, 256>>>(src, dst);
    k_node   <<<(NN + 7) / 8, 256>>>(W1, b1, g1, be1);

    // conv 2
    k_scale  <<<(NN * 16 + 255) / 256, 256>>>(h, 1);
    k_scatter<<<(NE * 16 + 255) / 256, 256>>>(src, dst);
    k_node   <<<(NN + 7) / 8, 256>>>(W2, b2, g2, be2);

    // pooling + head
    k_pool<<<(NN * 64 + 255) / 256, 256>>>(gid);
    k_cls <<<NG, 64>>>(Wc1, bc1, g3, be3, Wc2, bc2, g4, be4, Wc3, bc3, out);
}